// round 7
// baseline (speedup 1.0000x reference)
#include <cuda_runtime.h>
#include <cuda_fp16.h>
#include <cstdint>

#define B_  8
#define S_  512
#define D_  1024
#define V_  32000
#define ND_ 8

#define BM 256
#define BN 128
#define BK 32
#define NCHUNK (D_ / BK)        // 32

#define ROWB 80                 // smem bytes per row: 64 data + 16 pad (conflict-free)
#define A_STAGE_B (BM * ROWB)   // 20480
#define B_STAGE_B (BN * ROWB)   // 10240
#define OFF_A0 0
#define OFF_A1 A_STAGE_B
#define OFF_B0 (2 * A_STAGE_B)
#define OFF_B1 (2 * A_STAGE_B + B_STAGE_B)
#define SMEM_TOTAL (2 * A_STAGE_B + 2 * B_STAGE_B)   // 61440

__device__ __half g_hidden[B_ * S_ * D_];   // fp16 base-proj output
__device__ __half g_hs_h[B_ * S_ * D_];     // fp16 hidden_states

// ---------------- helpers ----------------
__device__ __forceinline__ uint32_t smem_u32(const void* p) {
    uint32_t a;
    asm("{ .reg .u64 t; cvta.to.shared.u64 t, %1; cvt.u32.u64 %0, t; }" : "=r"(a) : "l"(p));
    return a;
}
__device__ __forceinline__ uint32_t pack_h2(float x, float y) {
    uint32_t d;
    asm("cvt.rn.f16x2.f32 %0, %2, %1;" : "=r"(d) : "f"(x), "f"(y));
    return d;
}
__device__ __forceinline__ void cp16(uint32_t d, const void* s) {
    asm volatile("cp.async.cg.shared.global [%0], [%1], 16;" :: "r"(d), "l"(s));
}
__device__ __forceinline__ void ldsm_x4(uint32_t* r, uint32_t addr) {
    asm volatile("ldmatrix.sync.aligned.m8n8.x4.shared.b16 {%0,%1,%2,%3}, [%4];"
                 : "=r"(r[0]), "=r"(r[1]), "=r"(r[2]), "=r"(r[3]) : "r"(addr));
}
__device__ __forceinline__ void mma_f16(float* d, const uint32_t* a, const uint32_t* b) {
    asm volatile(
        "mma.sync.aligned.m16n8k16.row.col.f32.f16.f16.f32 "
        "{%0,%1,%2,%3}, {%4,%5,%6,%7}, {%8,%9}, {%0,%1,%2,%3};"
        : "+f"(d[0]), "+f"(d[1]), "+f"(d[2]), "+f"(d[3])
        : "r"(a[0]), "r"(a[1]), "r"(a[2]), "r"(a[3]), "r"(b[0]), "r"(b[1]));
}

// ---------------------------------------------------------------------------
template <bool HIDDEN_OUT>
__device__ __forceinline__ void gemm_tile(
    const __half* __restrict__ A,
    const float*  __restrict__ Bsrc,
    const float*  __restrict__ bias,
    float* __restrict__ C, __half* __restrict__ Chalf,
    int Nld, int m0, int n0)
{
    extern __shared__ char smem[];
    const uint32_t sb = smem_u32(smem);

    const int t    = threadIdx.x;
    const int lane = t & 31;
    const int wid  = t >> 5;
    const int wm   = wid >> 1;       // 0..3
    const int wn   = wid & 1;        // 0..1

    const int bn  = t & 127;
    const int bk0 = (t >> 7) * 16;

    // per-warp ldsm base offsets (row part), hoisted
    const int aRowOff = (wm * 64 + (lane & 15)) * ROWB + (lane >> 4) * 16;
    const int bRowOff = (wn * 64 + (lane & 7) + ((lane >> 4) ? 8 : 0)) * ROWB
                      + ((lane >> 3) & 1) * 16;

    float acc[4][8][4];
    #pragma unroll
    for (int mt = 0; mt < 4; mt++)
        #pragma unroll
        for (int nt = 0; nt < 8; nt++)
            #pragma unroll
            for (int r = 0; r < 4; r++) acc[mt][nt][r] = 0.0f;

    float vpre[16];
    uint32_t a0[4][4], b0[4][4];   // fragments for ks=0
    uint32_t a1[4][4], b1[4][4];   // fragments for ks=1

    // ---- prologue: stage chunk 0 ----
    {
        #pragma unroll
        for (int i = 0; i < 4; i++) {
            const int idx = i * 256 + t;
            const int row = idx >> 2, q = idx & 3;
            cp16(sb + OFF_A0 + row * ROWB + q * 16,
                 A + (size_t)(m0 + row) * D_ + q * 8);
        }
        asm volatile("cp.async.commit_group;" ::: "memory");

        const float* p = Bsrc + (size_t)bk0 * Nld + n0 + bn;
        #pragma unroll
        for (int kk = 0; kk < 16; kk++) vpre[kk] = p[(size_t)kk * Nld];

        uint32_t hw[8];
        #pragma unroll
        for (int j = 0; j < 8; j++) hw[j] = pack_h2(vpre[2*j], vpre[2*j+1]);
        const uint32_t dst = sb + OFF_B0 + bn * ROWB + bk0 * 2;
        asm volatile("st.shared.v4.b32 [%0], {%1,%2,%3,%4};" :: "r"(dst),
            "r"(hw[0]), "r"(hw[1]), "r"(hw[2]), "r"(hw[3]) : "memory");
        asm volatile("st.shared.v4.b32 [%0], {%1,%2,%3,%4};" :: "r"(dst + 16),
            "r"(hw[4]), "r"(hw[5]), "r"(hw[6]), "r"(hw[7]) : "memory");

        asm volatile("cp.async.wait_group 0;" ::: "memory");
        __syncthreads();

        // preload ks=0 fragments of chunk 0
        #pragma unroll
        for (int mt = 0; mt < 4; mt++)
            ldsm_x4(a0[mt], sb + OFF_A0 + aRowOff + mt * 16 * ROWB);
        #pragma unroll
        for (int p4 = 0; p4 < 4; p4++)
            ldsm_x4(b0[p4], sb + OFF_B0 + bRowOff + p4 * 16 * ROWB);
    }

    // ---- mainloop ----
    for (int c = 0; c < NCHUNK; c++) {
        const int buf = c & 1;
        const bool has_next = (c + 1 < NCHUNK);
        const uint32_t aBase  = sb + (buf ? OFF_A1 : OFF_A0);
        const uint32_t bBase  = sb + (buf ? OFF_B1 : OFF_B0);
        const uint32_t aBaseN = sb + (buf ? OFF_A0 : OFF_A1);
        const uint32_t bBaseN = sb + (buf ? OFF_B0 : OFF_B1);

        if (has_next) {
            const int k0n = (c + 1) * BK;
            #pragma unroll
            for (int i = 0; i < 4; i++) {
                const int idx = i * 256 + t;
                const int row = idx >> 2, q = idx & 3;
                cp16(aBaseN + row * ROWB + q * 16,
                     A + (size_t)(m0 + row) * D_ + k0n + q * 8);
            }
            asm volatile("cp.async.commit_group;" ::: "memory");
            const float* p = Bsrc + (size_t)(k0n + bk0) * Nld + n0 + bn;
            #pragma unroll
            for (int kk = 0; kk < 16; kk++) vpre[kk] = p[(size_t)kk * Nld];
        }

        // load ks=1 fragments (overlaps with ks=0 HMMAs below)
        #pragma unroll
        for (int mt = 0; mt < 4; mt++)
            ldsm_x4(a1[mt], aBase + aRowOff + mt * 16 * ROWB + 32);
        #pragma unroll
        for (int p4 = 0; p4 < 4; p4++)
            ldsm_x4(b1[p4], bBase + bRowOff + p4 * 16 * ROWB + 32);

        // ks=0 HMMA block
        #pragma unroll
        for (int mt = 0; mt < 4; mt++)
            #pragma unroll
            for (int p4 = 0; p4 < 4; p4++) {
                mma_f16(acc[mt][2*p4+0], a0[mt], &b0[p4][0]);
                mma_f16(acc[mt][2*p4+1], a0[mt], &b0[p4][2]);
            }

        // store next B tile (overlaps with ks=1 HMMAs)
        if (has_next) {
            uint32_t hw[8];
            #pragma unroll
            for (int j = 0; j < 8; j++) hw[j] = pack_h2(vpre[2*j], vpre[2*j+1]);
            const uint32_t dst = bBaseN + bn * ROWB + bk0 * 2;
            asm volatile("st.shared.v4.b32 [%0], {%1,%2,%3,%4};" :: "r"(dst),
                "r"(hw[0]), "r"(hw[1]), "r"(hw[2]), "r"(hw[3]) : "memory");
            asm volatile("st.shared.v4.b32 [%0], {%1,%2,%3,%4};" :: "r"(dst + 16),
                "r"(hw[4]), "r"(hw[5]), "r"(hw[6]), "r"(hw[7]) : "memory");
        }

        // ks=1 HMMA block
        #pragma unroll
        for (int mt = 0; mt < 4; mt++)
            #pragma unroll
            for (int p4 = 0; p4 < 4; p4++) {
                mma_f16(acc[mt][2*p4+0], a1[mt], &b1[p4][0]);
                mma_f16(acc[mt][2*p4+1], a1[mt], &b1[p4][2]);
            }

        if (has_next) {
            asm volatile("cp.async.wait_group 0;" ::: "memory");
            __syncthreads();
            // preload ks=0 fragments of next chunk right after barrier
            #pragma unroll
            for (int mt = 0; mt < 4; mt++)
                ldsm_x4(a0[mt], aBaseN + aRowOff + mt * 16 * ROWB);
            #pragma unroll
            for (int p4 = 0; p4 < 4; p4++)
                ldsm_x4(b0[p4], bBaseN + bRowOff + p4 * 16 * ROWB);
        }
    }

    // ---- epilogue ----
    const int gid = lane >> 2, tig = lane & 3;
    #pragma unroll
    for (int mt = 0; mt < 4; mt++) {
        const int r0 = m0 + wm * 64 + mt * 16 + gid;
        #pragma unroll
        for (int nt = 0; nt < 8; nt++) {
            const int col = n0 + wn * 64 + nt * 8 + tig * 2;
            const float2 bv = *reinterpret_cast<const float2*>(bias + col);
            const float o0x = acc[mt][nt][0] + bv.x, o0y = acc[mt][nt][1] + bv.y;
            const float o1x = acc[mt][nt][2] + bv.x, o1y = acc[mt][nt][3] + bv.y;
            if (HIDDEN_OUT) {
                *reinterpret_cast<uint32_t*>(Chalf + (size_t)r0 * Nld + col)       = pack_h2(o0x, o0y);
                *reinterpret_cast<uint32_t*>(Chalf + (size_t)(r0 + 8) * Nld + col) = pack_h2(o1x, o1y);
            } else {
                *reinterpret_cast<float2*>(C + (size_t)r0 * Nld + col)       = make_float2(o0x, o0y);
                *reinterpret_cast<float2*>(C + (size_t)(r0 + 8) * Nld + col) = make_float2(o1x, o1y);
            }
        }
    }
}

// ---------------- kernels ----------------
__global__ __launch_bounds__(256) void round_hs_kernel(const float* __restrict__ hs) {
    const int i = (blockIdx.x * 256 + threadIdx.x) * 4;
    float4 v = *reinterpret_cast<const float4*>(hs + i);
    uint2 o;
    o.x = pack_h2(v.x, v.y);
    o.y = pack_h2(v.z, v.w);
    *reinterpret_cast<uint2*>(g_hs_h + i) = o;
}

__global__ __launch_bounds__(256, 1) void gemm_base_kernel(
    const float* __restrict__ Wb, const float* __restrict__ bb)
{
    gemm_tile<true>(g_hs_h, Wb, bb, nullptr, g_hidden, D_,
                    blockIdx.y * BM, blockIdx.x * BN);
}

__global__ __launch_bounds__(256, 1) void gemm_heads_kernel(
    const int* __restrict__ dom, const float* __restrict__ Wh,
    const float* __restrict__ bh, float* __restrict__ out)
{
    const int b = blockIdx.z;
    const int id = dom[b];
    const int idx = (id >= 0 && id < ND_) ? id : ND_;
    gemm_tile<false>(g_hidden + (size_t)b * S_ * D_,
                     Wh + (size_t)idx * D_ * V_,
                     bh + (size_t)idx * V_,
                     out + (size_t)b * S_ * V_, nullptr,
                     V_, blockIdx.y * BM, blockIdx.x * BN);
}

// ---------------- launch ----------------
extern "C" void kernel_launch(void* const* d_in, const int* in_sizes, int n_in,
                              void* d_out, int out_size)
{
    const float* hs      = (const float*)d_in[0];
    const int*   dom     = (const int*)  d_in[1];
    const float* W_base  = (const float*)d_in[2];
    const float* b_base  = (const float*)d_in[3];
    const float* W_heads = (const float*)d_in[4];
    const float* b_heads = (const float*)d_in[5];
    float* out = (float*)d_out;

    static bool attr_set = false;
    if (!attr_set) {
        cudaFuncSetAttribute(gemm_base_kernel,  cudaFuncAttributeMaxDynamicSharedMemorySize, SMEM_TOTAL);
        cudaFuncSetAttribute(gemm_heads_kernel, cudaFuncAttributeMaxDynamicSharedMemorySize, SMEM_TOTAL);
        attr_set = true;
    }

    round_hs_kernel<<<(B_ * S_ * D_) / (256 * 4), 256>>>(hs);

    dim3 gA(D_ / BN, (B_ * S_) / BM, 1);          // (8, 16, 1)
    gemm_base_kernel<<<gA, 256, SMEM_TOTAL>>>(W_base, b_base);

    dim3 gB(V_ / BN, S_ / BM, B_);                // (250, 2, 8)
    gemm_heads_kernel<<<gB, 256, SMEM_TOTAL>>>(dom, W_heads, b_heads, out);
}